// round 1
// baseline (speedup 1.0000x reference)
#include <cuda_runtime.h>

#define NN 100000
#define NE 3200000
#define FULLMASK 0xffffffffu

// ---------------- device scratch (static: no allocations allowed) ----------------
__device__ int g_cnt[NN];
__device__ int g_rs[NN + 1];
__device__ int g_cur[NN];
__device__ int g_csr[NE];
__device__ int g_bsum[32];
__device__ int g_flag[1];
__device__ __align__(16) float g_h1[(size_t)NN * 128];
__device__ __align__(16) float g_hA[(size_t)NN * 128];
__device__ __align__(16) float g_al1[NN * 8];
__device__ __align__(16) float g_ar1[NN * 8];
__device__ __align__(16) float g_al2[NN * 8];
__device__ __align__(16) float g_ar2[NN * 8];
__device__ __align__(16) float g_wsrc[128 * 8];
__device__ __align__(16) float g_wdst[128 * 8];
__device__ __align__(16) float g_Wbig[1024 * 40];
__device__ __align__(16) float g_agg[(size_t)NN * 1024];

// ---------------- edge index access (int64 vs int32 tolerant) ----------------
__device__ __forceinline__ void edge_sd(const void* ei, int i32, int e, int& s, int& d) {
    if (i32) {
        const int* p = (const int*)ei;
        s = p[e];
        d = p[NE + e];
    } else {
        const long long* p = (const long long*)ei;
        s = (int)p[e];
        d = (int)p[NE + e];
    }
}

__global__ void k_detect(const long long* ei) {
    int t = threadIdx.x;
    int bad = 0;
    for (int i = t; i < 4096; i += 256) {
        long long v = ei[i];
        if (v < 0 || v >= NN) bad = 1;
    }
    if (__syncthreads_or(bad)) {
        if (t == 0) g_flag[0] = 1;
    }
}

__global__ void k_hist(const void* ei) {
    int e = blockIdx.x * blockDim.x + threadIdx.x;
    if (e >= NE) return;
    int i32 = g_flag[0];
    int s, d;
    edge_sd(ei, i32, e, s, d);
    atomicAdd(&g_cnt[d], 1);
}

// ---------------- exclusive scan of counts (3 kernels, chunk=4096) ----------------
__global__ void k_scan1() {
    __shared__ int sw[32];
    int b = blockIdx.x, t = threadIdx.x;
    int base = b * 4096 + t * 4;
    int s = 0;
#pragma unroll
    for (int j = 0; j < 4; j++) {
        int idx = base + j;
        s += (idx < NN) ? g_cnt[idx] : 0;
    }
#pragma unroll
    for (int o = 16; o; o >>= 1) s += __shfl_xor_sync(FULLMASK, s, o);
    if ((t & 31) == 0) sw[t >> 5] = s;
    __syncthreads();
    if (t < 32) {
        int v = sw[t];
#pragma unroll
        for (int o = 16; o; o >>= 1) v += __shfl_xor_sync(FULLMASK, v, o);
        if (t == 0) g_bsum[b] = v;
    }
}

__global__ void k_scan2(int nb) {
    int t = threadIdx.x;
    int v = (t < nb) ? g_bsum[t] : 0;
    int orig = v;
#pragma unroll
    for (int o = 1; o < 32; o <<= 1) {
        int y = __shfl_up_sync(FULLMASK, v, o);
        if (t >= o) v += y;
    }
    if (t < nb) g_bsum[t] = v - orig;
}

__global__ void k_scan3() {
    __shared__ int sw[32];
    int b = blockIdx.x, t = threadIdx.x;
    int lane = t & 31, w = t >> 5;
    int base = b * 4096 + t * 4;
    int v[4];
#pragma unroll
    for (int j = 0; j < 4; j++) {
        int idx = base + j;
        v[j] = (idx < NN) ? g_cnt[idx] : 0;
    }
    int tl = v[0] + v[1] + v[2] + v[3];
    int x = tl;
#pragma unroll
    for (int o = 1; o < 32; o <<= 1) {
        int y = __shfl_up_sync(FULLMASK, x, o);
        if (lane >= o) x += y;
    }
    if (lane == 31) sw[w] = x;
    __syncthreads();
    if (w == 0) {
        int z = sw[lane];
#pragma unroll
        for (int o = 1; o < 32; o <<= 1) {
            int y = __shfl_up_sync(FULLMASK, z, o);
            if (lane >= o) z += y;
        }
        sw[lane] = z;
    }
    __syncthreads();
    int woff = (w > 0) ? sw[w - 1] : 0;
    int run = g_bsum[b] + woff + (x - tl);
#pragma unroll
    for (int j = 0; j < 4; j++) {
        int idx = base + j;
        if (idx <= NN) {
            g_rs[idx] = run;
            if (idx < NN) g_cur[idx] = run;
        }
        run += v[j];
    }
}

__global__ void k_fill(const void* ei) {
    int e = blockIdx.x * blockDim.x + threadIdx.x;
    if (e >= NE) return;
    int i32 = g_flag[0];
    int s, d;
    edge_sd(ei, i32, e, s, d);
    int pos = atomicAdd(&g_cur[d], 1);
    g_csr[pos] = s;
}

// ---------------- GEMM1: h1 = x @ W1   [NN,128] x [128,128] ----------------
__global__ __launch_bounds__(256) void k_gemm1(const float* __restrict__ x,
                                               const float* __restrict__ W1) {
    __shared__ float xs[64][32];
    __shared__ float ws[32][128];
    int t = threadIdx.x;
    int n0 = blockIdx.x * 64;
    int tx = t & 31, ty = t >> 5;  // ty in [0,8): rows ty*8..+7 ; tx: cols tx*4..+3
    float acc[8][4];
#pragma unroll
    for (int i = 0; i < 8; i++)
#pragma unroll
        for (int j = 0; j < 4; j++) acc[i][j] = 0.f;

    for (int k0 = 0; k0 < 128; k0 += 32) {
#pragma unroll
        for (int i = 0; i < 8; i++) {
            int f = t + i * 256;
            int r = f >> 5, kk = f & 31;
            int row = n0 + r;
            xs[r][kk] = (row < NN) ? x[(size_t)row * 128 + k0 + kk] : 0.f;
        }
#pragma unroll
        for (int i = 0; i < 4; i++) {
            int f = t + i * 256;
            int kr = f >> 5, c4 = f & 31;
            *(float4*)&ws[kr][c4 * 4] = *(const float4*)&W1[(size_t)(k0 + kr) * 128 + c4 * 4];
        }
        __syncthreads();
#pragma unroll
        for (int k = 0; k < 32; k++) {
            float4 bv = *(float4*)&ws[k][tx * 4];
#pragma unroll
            for (int i = 0; i < 8; i++) {
                float a = xs[ty * 8 + i][k];
                acc[i][0] += a * bv.x;
                acc[i][1] += a * bv.y;
                acc[i][2] += a * bv.z;
                acc[i][3] += a * bv.w;
            }
        }
        __syncthreads();
    }
#pragma unroll
    for (int i = 0; i < 8; i++) {
        int row = n0 + ty * 8 + i;
        if (row < NN) {
            float4 o = make_float4(acc[i][0], acc[i][1], acc[i][2], acc[i][3]);
            *(float4*)&g_h1[(size_t)row * 128 + tx * 4] = o;
        }
    }
}

// ---------------- alpha1: per-node attention logits for layer 1 ----------------
__global__ void k_alpha1(const float* __restrict__ as1, const float* __restrict__ ad1) {
    int gw = (blockIdx.x * blockDim.x + threadIdx.x) >> 5;
    int lane = threadIdx.x & 31;
    if (gw >= NN) return;
    float4 hv = ((const float4*)g_h1)[(size_t)gw * 32 + lane];
    float4 wsv = ((const float4*)as1)[lane];
    float4 wdv = ((const float4*)ad1)[lane];
    float s = hv.x * wsv.x + hv.y * wsv.y + hv.z * wsv.z + hv.w * wsv.w;
    float d = hv.x * wdv.x + hv.y * wdv.y + hv.z * wdv.z + hv.w * wdv.w;
    s += __shfl_xor_sync(FULLMASK, s, 1);
    s += __shfl_xor_sync(FULLMASK, s, 2);
    d += __shfl_xor_sync(FULLMASK, d, 1);
    d += __shfl_xor_sync(FULLMASK, d, 2);
    if ((lane & 3) == 0) {
        int head = lane >> 2;
        g_al1[gw * 8 + head] = s;
        g_ar1[gw * 8 + head] = d;
    }
}

__device__ __forceinline__ float lrelu(float e) { return fmaxf(e, 0.2f * e); }

// ---------------- edge kernel layer 1: warp per destination ----------------
__global__ __launch_bounds__(256) void k_edge1(const float* __restrict__ b1) {
    int gw = (blockIdx.x * blockDim.x + threadIdx.x) >> 5;
    int lane = threadIdx.x & 31;
    if (gw >= NN) return;
    int n = gw;
    int beg = g_rs[n], end = g_rs[n + 1];
    int deg = end - beg;
    int head = lane >> 2;

    float ar8[8];
    {
        const float4* p = (const float4*)(g_ar1 + n * 8);
        float4 a = p[0], b = p[1];
        ar8[0] = a.x; ar8[1] = a.y; ar8[2] = a.z; ar8[3] = a.w;
        ar8[4] = b.x; ar8[5] = b.y; ar8[6] = b.z; ar8[7] = b.w;
    }
    float m8[8];
#pragma unroll
    for (int h = 0; h < 8; h++) m8[h] = -1e30f;

#pragma unroll 2
    for (int j = lane; j < deg; j += 32) {
        int s = g_csr[beg + j];
        const float4* p = (const float4*)(g_al1 + s * 8);
        float4 a = p[0], b = p[1];
        float al8[8] = {a.x, a.y, a.z, a.w, b.x, b.y, b.z, b.w};
#pragma unroll
        for (int h = 0; h < 8; h++) {
            float e = lrelu(al8[h] + ar8[h]);
            m8[h] = fmaxf(m8[h], e);
        }
    }
#pragma unroll
    for (int h = 0; h < 8; h++) {
#pragma unroll
        for (int o = 16; o; o >>= 1) m8[h] = fmaxf(m8[h], __shfl_xor_sync(FULLMASK, m8[h], o));
    }
    float m_h = m8[0], ar_h = ar8[0];
#pragma unroll
    for (int h = 1; h < 8; h++) {
        if (head == h) { m_h = m8[h]; ar_h = ar8[h]; }
    }

    float4 acc = make_float4(0.f, 0.f, 0.f, 0.f);
    float den = 0.f;
    const float4* hp = (const float4*)g_h1;
#pragma unroll 4
    for (int j = 0; j < deg; j++) {
        int s = g_csr[beg + j];
        float e = lrelu(g_al1[s * 8 + head] + ar_h);
        float p = __expf(e - m_h);
        den += p;
        float4 hv = hp[(size_t)s * 32 + lane];
        acc.x += p * hv.x;
        acc.y += p * hv.y;
        acc.z += p * hv.z;
        acc.w += p * hv.w;
    }
    float inv = (deg > 0) ? 1.0f / den : 0.0f;
    float4 bb = ((const float4*)b1)[lane];
    float4 o;
    o.x = acc.x * inv + bb.x;
    o.y = acc.y * inv + bb.y;
    o.z = acc.z * inv + bb.z;
    o.w = acc.w * inv + bb.w;
    // ELU
    o.x = o.x > 0.f ? o.x : (__expf(o.x) - 1.f);
    o.y = o.y > 0.f ? o.y : (__expf(o.y) - 1.f);
    o.z = o.z > 0.f ? o.z : (__expf(o.z) - 1.f);
    o.w = o.w > 0.f ? o.w : (__expf(o.w) - 1.f);
    ((float4*)g_hA)[(size_t)n * 32 + lane] = o;
}

// ---------------- layer-2 weight preprocessing ----------------
__global__ void k_prep_eff(const float* __restrict__ W2, const float* __restrict__ as2,
                           const float* __restrict__ ad2) {
    int t = blockIdx.x * blockDim.x + threadIdx.x;
    if (t >= 1024) return;
    int k = t >> 3, h = t & 7;
    float s = 0.f, d = 0.f;
    for (int c = 0; c < 40; c++) {
        float w = W2[k * 320 + h * 40 + c];
        s += w * as2[h * 40 + c];
        d += w * ad2[h * 40 + c];
    }
    g_wsrc[t] = s;  // layout [k][h] = k*8+h
    g_wdst[t] = d;
}

__global__ void k_prep_wbig(const float* __restrict__ W2) {
    int t = blockIdx.x * blockDim.x + threadIdx.x;
    if (t >= 40960) return;
    int i = t / 40, c = t % 40;
    int h = i >> 7, k = i & 127;
    g_Wbig[t] = W2[k * 320 + h * 40 + c] * 0.125f;  // fold mean over heads
}

// ---------------- alpha2: al2/ar2 = hA @ w_eff  (warp grid-stride) ----------------
__global__ __launch_bounds__(256) void k_alpha2() {
    int wid = (blockIdx.x * blockDim.x + threadIdx.x) >> 5;
    int lane = threadIdx.x & 31;
    int nwarp = (gridDim.x * blockDim.x) >> 5;
    float ws[4][8], wd[4][8];
#pragma unroll
    for (int j = 0; j < 4; j++) {
        int k = lane * 4 + j;
        float4 a = ((const float4*)(g_wsrc + k * 8))[0];
        float4 b = ((const float4*)(g_wsrc + k * 8))[1];
        ws[j][0] = a.x; ws[j][1] = a.y; ws[j][2] = a.z; ws[j][3] = a.w;
        ws[j][4] = b.x; ws[j][5] = b.y; ws[j][6] = b.z; ws[j][7] = b.w;
        float4 c = ((const float4*)(g_wdst + k * 8))[0];
        float4 d = ((const float4*)(g_wdst + k * 8))[1];
        wd[j][0] = c.x; wd[j][1] = c.y; wd[j][2] = c.z; wd[j][3] = c.w;
        wd[j][4] = d.x; wd[j][5] = d.y; wd[j][6] = d.z; wd[j][7] = d.w;
    }
    for (int n = wid; n < NN; n += nwarp) {
        float4 hv = ((const float4*)g_hA)[(size_t)n * 32 + lane];
        float hvv[4] = {hv.x, hv.y, hv.z, hv.w};
        float as[8], ad[8];
#pragma unroll
        for (int h = 0; h < 8; h++) { as[h] = 0.f; ad[h] = 0.f; }
#pragma unroll
        for (int j = 0; j < 4; j++)
#pragma unroll
            for (int h = 0; h < 8; h++) {
                as[h] += hvv[j] * ws[j][h];
                ad[h] += hvv[j] * wd[j][h];
            }
#pragma unroll
        for (int h = 0; h < 8; h++) {
#pragma unroll
            for (int o = 16; o; o >>= 1) {
                as[h] += __shfl_xor_sync(FULLMASK, as[h], o);
                ad[h] += __shfl_xor_sync(FULLMASK, ad[h], o);
            }
        }
        if (lane == 0) {
#pragma unroll
            for (int h = 0; h < 8; h++) {
                g_al2[n * 8 + h] = as[h];
                g_ar2[n * 8 + h] = ad[h];
            }
        }
    }
}

// ---------------- edge kernel layer 2: aggregate in 128-dim input space ----------------
__global__ __launch_bounds__(256) void k_edge2() {
    int gw = (blockIdx.x * blockDim.x + threadIdx.x) >> 5;
    int lane = threadIdx.x & 31;
    if (gw >= NN) return;
    int n = gw;
    int beg = g_rs[n], end = g_rs[n + 1];
    int deg = end - beg;
    int hsel = lane & 7;

    float ar8[8];
    {
        const float4* p = (const float4*)(g_ar2 + n * 8);
        float4 a = p[0], b = p[1];
        ar8[0] = a.x; ar8[1] = a.y; ar8[2] = a.z; ar8[3] = a.w;
        ar8[4] = b.x; ar8[5] = b.y; ar8[6] = b.z; ar8[7] = b.w;
    }
    float m8[8];
#pragma unroll
    for (int h = 0; h < 8; h++) m8[h] = -1e30f;

#pragma unroll 2
    for (int j = lane; j < deg; j += 32) {
        int s = g_csr[beg + j];
        const float4* p = (const float4*)(g_al2 + s * 8);
        float4 a = p[0], b = p[1];
        float al8[8] = {a.x, a.y, a.z, a.w, b.x, b.y, b.z, b.w};
#pragma unroll
        for (int h = 0; h < 8; h++) {
            float e = lrelu(al8[h] + ar8[h]);
            m8[h] = fmaxf(m8[h], e);
        }
    }
#pragma unroll
    for (int h = 0; h < 8; h++) {
#pragma unroll
        for (int o = 16; o; o >>= 1) m8[h] = fmaxf(m8[h], __shfl_xor_sync(FULLMASK, m8[h], o));
    }
    float m_o = m8[0], ar_o = ar8[0];
#pragma unroll
    for (int h = 1; h < 8; h++) {
        if (hsel == h) { m_o = m8[h]; ar_o = ar8[h]; }
    }

    float4 acc[8];
#pragma unroll
    for (int h = 0; h < 8; h++) acc[h] = make_float4(0.f, 0.f, 0.f, 0.f);
    float den = 0.f;
    const float4* hp = (const float4*)g_hA;
#pragma unroll 2
    for (int j = 0; j < deg; j++) {
        int s = g_csr[beg + j];
        float e = lrelu(g_al2[s * 8 + hsel] + ar_o);
        float p = __expf(e - m_o);
        den += p;
        float4 hv = hp[(size_t)s * 32 + lane];
#pragma unroll
        for (int h = 0; h < 8; h++) {
            float ph = __shfl_sync(FULLMASK, p, h);
            acc[h].x += ph * hv.x;
            acc[h].y += ph * hv.y;
            acc[h].z += ph * hv.z;
            acc[h].w += ph * hv.w;
        }
    }
    float4* ap = (float4*)(g_agg + (size_t)n * 1024);
#pragma unroll
    for (int h = 0; h < 8; h++) {
        float dh = __shfl_sync(FULLMASK, den, h);
        float iv = (deg > 0) ? 1.0f / dh : 0.0f;
        float4 o = make_float4(acc[h].x * iv, acc[h].y * iv, acc[h].z * iv, acc[h].w * iv);
        ap[h * 32 + lane] = o;
    }
}

// ---------------- GEMM3: out = agg[N,1024] @ Wbig[1024,40] + b2 ----------------
__global__ __launch_bounds__(256) void k_gemm3(const float* __restrict__ b2,
                                               float* __restrict__ out) {
    __shared__ float As[32][129];
    __shared__ float Bs[32][41];
    int t = threadIdx.x;
    int n0 = blockIdx.x * 128;
    int tx = t & 7;   // col group: cols tx*5..+4
    int ty = t >> 3;  // row group: rows ty*4..+3
    float acc[4][5];
#pragma unroll
    for (int i = 0; i < 4; i++)
#pragma unroll
        for (int j = 0; j < 5; j++) acc[i][j] = 0.f;

    for (int k0 = 0; k0 < 1024; k0 += 32) {
#pragma unroll
        for (int i = 0; i < 4; i++) {
            int f = t + i * 256;
            int row = f >> 3, kq = f & 7;
            int n = n0 + row;
            float4 v = (n < NN) ? *(const float4*)&g_agg[(size_t)n * 1024 + k0 + kq * 4]
                                : make_float4(0.f, 0.f, 0.f, 0.f);
            As[kq * 4 + 0][row] = v.x;
            As[kq * 4 + 1][row] = v.y;
            As[kq * 4 + 2][row] = v.z;
            As[kq * 4 + 3][row] = v.w;
        }
#pragma unroll
        for (int i = 0; i < 5; i++) {
            int f = t + i * 256;
            int k = f / 40, c = f % 40;
            Bs[k][c] = g_Wbig[(k0 + k) * 40 + c];
        }
        __syncthreads();
#pragma unroll
        for (int k = 0; k < 32; k++) {
            float a[4], bv[5];
#pragma unroll
            for (int i = 0; i < 4; i++) a[i] = As[k][ty * 4 + i];
#pragma unroll
            for (int j = 0; j < 5; j++) bv[j] = Bs[k][tx * 5 + j];
#pragma unroll
            for (int i = 0; i < 4; i++)
#pragma unroll
                for (int j = 0; j < 5; j++) acc[i][j] += a[i] * bv[j];
        }
        __syncthreads();
    }
#pragma unroll
    for (int i = 0; i < 4; i++) {
        int n = n0 + ty * 4 + i;
        if (n < NN) {
#pragma unroll
            for (int j = 0; j < 5; j++) out[(size_t)n * 40 + tx * 5 + j] = acc[i][j] + b2[tx * 5 + j];
        }
    }
}

// ---------------- host launcher ----------------
extern "C" void kernel_launch(void* const* d_in, const int* in_sizes, int n_in,
                              void* d_out, int out_size) {
    const float* x   = (const float*)d_in[0];
    const void*  ei  = d_in[1];
    const float* W1  = (const float*)d_in[2];
    const float* as1 = (const float*)d_in[3];
    const float* ad1 = (const float*)d_in[4];
    const float* b1  = (const float*)d_in[5];
    const float* W2  = (const float*)d_in[6];
    const float* as2 = (const float*)d_in[7];
    const float* ad2 = (const float*)d_in[8];
    const float* b2  = (const float*)d_in[9];
    float* out = (float*)d_out;

    static int* cnt_p = nullptr;
    static int* flag_p = nullptr;
    if (!cnt_p) {
        cudaGetSymbolAddress((void**)&cnt_p, g_cnt);
        cudaGetSymbolAddress((void**)&flag_p, g_flag);
    }
    cudaMemsetAsync(cnt_p, 0, NN * sizeof(int));
    cudaMemsetAsync(flag_p, 0, sizeof(int));

    k_detect<<<1, 256>>>((const long long*)ei);
    k_hist<<<(NE + 255) / 256, 256>>>(ei);
    k_scan1<<<25, 1024>>>();
    k_scan2<<<1, 32>>>(25);
    k_scan3<<<25, 1024>>>();
    k_fill<<<(NE + 255) / 256, 256>>>(ei);

    k_gemm1<<<(NN + 63) / 64, 256>>>(x, W1);
    k_alpha1<<<(NN * 32 + 255) / 256, 256>>>(as1, ad1);
    k_edge1<<<(NN * 32 + 255) / 256, 256>>>(b1);

    k_prep_eff<<<4, 256>>>(W2, as2, ad2);
    k_prep_wbig<<<160, 256>>>(W2);
    k_alpha2<<<592, 256>>>();
    k_edge2<<<(NN * 32 + 255) / 256, 256>>>();
    k_gemm3<<<(NN + 127) / 128, 256>>>(b2, out);
}